// round 1
// baseline (speedup 1.0000x reference)
#include <cuda_runtime.h>
#include <cuda_fp16.h>

#define U   256
#define INP 64
#define TT  128
#define BB  256
#define UNFOLDS 6
#define EPSV 1e-8f

// ---------------- packed parameter scratch (device globals; no allocs) -------------
// Recurrent synapses, i paired along the reduction dim (i2 = i>>1):
//   g_rs2[i2*U + j] = half2( 0.5*sigma[2i2][j],   0.5*sigma[2i2+1][j] )
//   g_rc [i2*U + j] = float2(-0.5*sigma*mu[2i2][j], ... [2i2+1][j] )
//   g_ran[i2*U + j] = half2( 0.5*w*erev[2i2][j],  ... )
__device__ __half2 g_rs2[(U/2) * U];
__device__ float2  g_rc [(U/2) * U];
__device__ __half2 g_ran[(U/2) * U];
// Sensory synapses (input_w/input_b folded in): z = (0.5*ss*iw)*x + 0.5*ss*(ib - smu)
__device__ __half2 g_ss2[(INP/2) * U];
__device__ float2  g_sc [(INP/2) * U];
__device__ __half2 g_san[(INP/2) * U];
// Column constants: Cn = sum_i an, Cd = sum_i |an|
__device__ float g_CnR[U], g_CdR[U], g_CnS[U], g_CdS[U];

__device__ __forceinline__ float tanh_ap(float x) {
    float r;
    asm("tanh.approx.f32 %0, %1;" : "=f"(r) : "f"(x));
    return r;
}

// ---------------- prep kernels ----------------
__global__ void prep_rec(const float* __restrict__ mu, const float* __restrict__ sg,
                         const float* __restrict__ w,  const float* __restrict__ er) {
    int idx = blockIdx.x * blockDim.x + threadIdx.x;   // U*U
    if (idx >= U * U) return;
    int i = idx / U, j = idx % U;
    float s2 = 0.5f * sg[idx];
    float c  = -s2 * mu[idx];
    float an = 0.5f * w[idx] * er[idx];
    int i2 = i >> 1, lo = i & 1;
    ((__half*)g_rs2)[(i2 * U + j) * 2 + lo] = __float2half_rn(s2);
    ((float*)g_rc )[(i2 * U + j) * 2 + lo] = c;
    ((__half*)g_ran)[(i2 * U + j) * 2 + lo] = __float2half_rn(an);
}

__global__ void prep_rec_cols(const float* __restrict__ w, const float* __restrict__ er) {
    int j = threadIdx.x;   // 256 threads
    float cn = 0.f, cd = 0.f;
    for (int i = 0; i < U; i++) {
        float a = 0.5f * w[i * U + j];
        cn += a * er[i * U + j];
        cd += a;
    }
    g_CnR[j] = cn; g_CdR[j] = cd;
}

__global__ void prep_sens(const float* __restrict__ smu, const float* __restrict__ ssg,
                          const float* __restrict__ sw,  const float* __restrict__ ser,
                          const float* __restrict__ iw,  const float* __restrict__ ib) {
    int idx = blockIdx.x * blockDim.x + threadIdx.x;   // INP*U
    if (idx >= INP * U) return;
    int i = idx / U, j = idx % U;
    float hs = 0.5f * ssg[idx];
    float s2 = hs * iw[i];
    float c  = hs * (ib[i] - smu[idx]);
    float an = 0.5f * sw[idx] * ser[idx];
    int i2 = i >> 1, lo = i & 1;
    ((__half*)g_ss2)[(i2 * U + j) * 2 + lo] = __float2half_rn(s2);
    ((float*)g_sc )[(i2 * U + j) * 2 + lo] = c;
    ((__half*)g_san)[(i2 * U + j) * 2 + lo] = __float2half_rn(an);
}

__global__ void prep_sens_cols(const float* __restrict__ sw, const float* __restrict__ ser) {
    int j = threadIdx.x;
    float cn = 0.f, cd = 0.f;
    for (int i = 0; i < INP; i++) {
        float a = 0.5f * sw[i * U + j];
        cn += a * ser[i * U + j];
        cd += a;
    }
    g_CnS[j] = cn; g_CdS[j] = cd;
}

// ---------------- main recurrence kernel ----------------
// grid = B/2 blocks, 512 threads: tid -> g = tid>>8 (which batch of the pair), j = tid&255.
__global__ void __launch_bounds__(512) ltc_main(
    const float* __restrict__ x,      // (B,T,INP)
    const float* __restrict__ ts,     // (B,T,1)
    const float* __restrict__ gleak, const float* __restrict__ vleak,
    const float* __restrict__ cm,
    const float* __restrict__ ow, const float* __restrict__ ob,
    const float* __restrict__ hw, const float* __restrict__ hb,
    float* __restrict__ out)
{
    __shared__ float v_s[2][U];
    __shared__ float x_s[2][INP];
    __shared__ float red[2][U];

    int tid = threadIdx.x;
    int g = tid >> 8;          // 0 or 1
    int j = tid & (U - 1);
    int b = blockIdx.x * 2 + g;

    float cm_j  = cm[j];
    float gl_j  = gleak[j];
    float glvl  = gl_j * vleak[j];
    float CnR = g_CnR[j], CdR = g_CdR[j];
    float CnS = g_CnS[j], CdS = g_CdS[j];

    float v = 0.f;
    v_s[g][j] = 0.f;
    __syncthreads();

    const __half2* ps2 = g_rs2 + j;
    const float2*  pc  = g_rc  + j;
    const __half2* pan = g_ran + j;
    const __half2* qs2 = g_ss2 + j;
    const float2*  qc  = g_sc  + j;
    const __half2* qan = g_san + j;

    const float* xb = x + (size_t)b * TT * INP;

    for (int t = 0; t < TT; t++) {
        // stage this timestep's inputs for both batches (all prior reads are
        // behind the last unfold's barrier)
        if (tid < INP)            x_s[0][tid]        = x[(size_t)(blockIdx.x * 2)     * TT * INP + t * INP + tid];
        else if (tid < 2 * INP)   x_s[1][tid - INP]  = x[(size_t)(blockIdx.x * 2 + 1) * TT * INP + t * INP + (tid - INP)];
        __syncthreads();

        float el  = ts[b * TT + t];
        float cmt = (6.0f * cm_j) / el;

        // sensory sums for this (b, j)
        float sN = CnS, sD = CdS;
        #pragma unroll 4
        for (int i2 = 0; i2 < INP / 2; i2++) {
            float2 s2 = __half22float2(qs2[i2 * U]);
            float2 c  = qc[i2 * U];
            float2 an = __half22float2(qan[i2 * U]);
            float xa = x_s[g][2 * i2], xbv = x_s[g][2 * i2 + 1];
            float t0 = tanh_ap(fmaf(s2.x, xa,  c.x));
            float t1 = tanh_ap(fmaf(s2.y, xbv, c.y));
            sN = fmaf(an.x, t0, sN); sD = fmaf(fabsf(an.x), t0, sD);
            sN = fmaf(an.y, t1, sN); sD = fmaf(fabsf(an.y), t1, sD);
        }

        float bN = glvl + CnR + sN;                  // numerator constant
        float bD = cmt + gl_j + CdR + sD + EPSV;     // denominator constant

        for (int u = 0; u < UNFOLDS; u++) {
            float aN = 0.f, aD = 0.f;
            #pragma unroll 4
            for (int i2 = 0; i2 < U / 2; i2++) {
                float2 s2 = __half22float2(ps2[i2 * U]);
                float2 c  = pc[i2 * U];
                float2 an = __half22float2(pan[i2 * U]);
                float2 vv = *(const float2*)&v_s[g][2 * i2];
                float t0 = tanh_ap(fmaf(s2.x, vv.x, c.x));
                float t1 = tanh_ap(fmaf(s2.y, vv.y, c.y));
                aN = fmaf(an.x, t0, aN); aD = fmaf(fabsf(an.x), t0, aD);
                aN = fmaf(an.y, t1, aN); aD = fmaf(fabsf(an.y), t1, aD);
            }
            float nv = fmaf(cmt, v, bN + aN) / (bD + aD);
            __syncthreads();              // all reads of v_s complete
            v = nv;
            v_s[g][j] = v;
            __syncthreads();              // new v_s visible
        }
    }

    // head: out[b] = sum_j (v*ow + ob) * hw + hb
    red[g][j] = fmaf(v, ow[j], ob[j]) * hw[j];
    __syncthreads();
    #pragma unroll
    for (int s = U / 2; s > 0; s >>= 1) {
        if (j < s) red[g][j] += red[g][j + s];
        __syncthreads();
    }
    if (j == 0) out[b] = red[g][0] + hb[0];
}

// ---------------- launch ----------------
extern "C" void kernel_launch(void* const* d_in, const int* in_sizes, int n_in,
                              void* d_out, int out_size) {
    const float* x     = (const float*)d_in[0];
    const float* ts    = (const float*)d_in[1];
    const float* smu   = (const float*)d_in[2];
    const float* ssg   = (const float*)d_in[3];
    const float* sw    = (const float*)d_in[4];
    const float* ser   = (const float*)d_in[5];
    const float* mu    = (const float*)d_in[6];
    const float* sg    = (const float*)d_in[7];
    const float* w     = (const float*)d_in[8];
    const float* er    = (const float*)d_in[9];
    const float* gleak = (const float*)d_in[10];
    const float* vleak = (const float*)d_in[11];
    const float* cm    = (const float*)d_in[12];
    const float* iw    = (const float*)d_in[13];
    const float* ib    = (const float*)d_in[14];
    const float* ow    = (const float*)d_in[15];
    const float* ob    = (const float*)d_in[16];
    const float* hw    = (const float*)d_in[17];
    const float* hb    = (const float*)d_in[18];
    float* out = (float*)d_out;

    prep_rec<<<(U * U + 255) / 256, 256>>>(mu, sg, w, er);
    prep_rec_cols<<<1, U>>>(w, er);
    prep_sens<<<(INP * U + 255) / 256, 256>>>(smu, ssg, sw, ser, iw, ib);
    prep_sens_cols<<<1, U>>>(sw, ser);
    ltc_main<<<BB / 2, 512>>>(x, ts, gleak, vleak, cm, ow, ob, hw, hb, out);
}

// round 3
// speedup vs baseline: 2.5250x; 2.5250x over previous
#include <cuda_runtime.h>
#include <cuda_fp16.h>
#include <cstdint>
#include <cstddef>

#define U   256
#define INP 64
#define TT  128
#define BB  256
#define UNFOLDS 6
#define EPSV 1e-8f
#define NTHR 256          // 4 batch-pairs x 64 j-columns
#define SMEM_BYTES (131072 + 32768 + 16384 + 2048 + 32 + 2048 + 128)

// ---------------- packed parameter scratch (device globals; no allocs) -------------
__device__ __half2 g_rs2[(U/2) * U];
__device__ float2  g_rc [(U/2) * U];
__device__ __half2 g_ran[(U/2) * U];
__device__ __half2 g_ss2[(INP/2) * U];
__device__ float2  g_sc [(INP/2) * U];
__device__ __half2 g_san[(INP/2) * U];
__device__ float g_CnR[U], g_CdR[U], g_CnS[U], g_CdS[U];

__device__ __forceinline__ float tanh_ap(float x) {
    float r;
    asm("tanh.approx.f32 %0, %1;" : "=f"(r) : "f"(x));
    return r;
}
__device__ __forceinline__ uint32_t smem_u32(const void* p) {
    uint32_t a;
    asm("{ .reg .u64 t; cvta.to.shared.u64 t, %1; cvt.u32.u64 %0, t; }" : "=r"(a) : "l"(p));
    return a;
}
__device__ __forceinline__ uint32_t mapa_rank(uint32_t a, uint32_t r) {
    uint32_t o;
    asm("mapa.shared::cluster.u32 %0, %1, %2;" : "=r"(o) : "r"(a), "r"(r));
    return o;
}
__device__ __forceinline__ void st_cluster_f32(uint32_t a, float v) {
    asm volatile("st.shared::cluster.f32 [%0], %1;" :: "r"(a), "f"(v) : "memory");
}

// ---------------- prep kernels (unchanged numerics from passing R1) ----------------
__global__ void prep_rec(const float* __restrict__ mu, const float* __restrict__ sg,
                         const float* __restrict__ w,  const float* __restrict__ er) {
    int idx = blockIdx.x * blockDim.x + threadIdx.x;
    if (idx >= U * U) return;
    int i = idx / U, j = idx % U;
    float s2 = 0.5f * sg[idx];
    float c  = -s2 * mu[idx];
    float an = 0.5f * w[idx] * er[idx];
    int i2 = i >> 1, lo = i & 1;
    ((__half*)g_rs2)[(i2 * U + j) * 2 + lo] = __float2half_rn(s2);
    ((float*)g_rc )[(i2 * U + j) * 2 + lo] = c;
    ((__half*)g_ran)[(i2 * U + j) * 2 + lo] = __float2half_rn(an);
}
__global__ void prep_rec_cols(const float* __restrict__ w, const float* __restrict__ er) {
    int j = threadIdx.x;
    float cn = 0.f, cd = 0.f;
    for (int i = 0; i < U; i++) {
        float a = 0.5f * w[i * U + j];
        cn += a * er[i * U + j];
        cd += a;
    }
    g_CnR[j] = cn; g_CdR[j] = cd;
}
__global__ void prep_sens(const float* __restrict__ smu, const float* __restrict__ ssg,
                          const float* __restrict__ sw,  const float* __restrict__ ser,
                          const float* __restrict__ iw,  const float* __restrict__ ib) {
    int idx = blockIdx.x * blockDim.x + threadIdx.x;
    if (idx >= INP * U) return;
    int i = idx / U, j = idx % U;
    float hs = 0.5f * ssg[idx];
    float s2 = hs * iw[i];
    float c  = hs * (ib[i] - smu[idx]);
    float an = 0.5f * sw[idx] * ser[idx];
    int i2 = i >> 1, lo = i & 1;
    ((__half*)g_ss2)[(i2 * U + j) * 2 + lo] = __float2half_rn(s2);
    ((float*)g_sc )[(i2 * U + j) * 2 + lo] = c;
    ((__half*)g_san)[(i2 * U + j) * 2 + lo] = __float2half_rn(an);
}
__global__ void prep_sens_cols(const float* __restrict__ sw, const float* __restrict__ ser) {
    int j = threadIdx.x;
    float cn = 0.f, cd = 0.f;
    for (int i = 0; i < INP; i++) {
        float a = 0.5f * sw[i * U + j];
        cn += a * ser[i * U + j];
        cd += a;
    }
    g_CnS[j] = cn; g_CdS[j] = cd;
}

// ---------------- main recurrence kernel: 4-CTA cluster, smem-resident params -------
// cluster of 4 CTAs covers 8 batches; CTA rank r owns j in [r*64, r*64+64).
// thread = (batch-pair bp 0..3, j-local jl 0..63); each thread handles 2 batches.
__global__ void __launch_bounds__(NTHR, 1) __cluster_dims__(4, 1, 1)
ltc_main(const float* __restrict__ x, const float* __restrict__ ts,
         const float* __restrict__ gleak, const float* __restrict__ vleak,
         const float* __restrict__ cm,
         const float* __restrict__ ow, const float* __restrict__ ob,
         const float* __restrict__ hw, const float* __restrict__ hb,
         float* __restrict__ out)
{
    extern __shared__ float4 dsm[];
    float4* rec  = dsm;                         // [128*64] 16B/pair   = 128 KB
    float4* sen  = dsm + 128 * 64;              // [32*64]             = 32 KB
    float*  vbuf = (float*)(sen + 32 * 64);     // [2][8][256]         = 16 KB
    float*  xs   = vbuf + 2 * 8 * 256;          // [8][64]             = 2 KB
    float*  tss  = xs + 8 * 64;                 // [8]
    float*  red  = tss + 8;                     // [8][64]             = 2 KB
    float*  part = red + 8 * 64;                // [4][8]

    int tid = threadIdx.x;
    uint32_t rank;
    asm("mov.u32 %0, %%cluster_ctarank;" : "=r"(rank));

    // ---- stage parameters for this CTA's 64 columns into smem ----
    for (int idx = tid; idx < 128 * 64; idx += NTHR) {
        int i2 = idx >> 6;
        int j  = (int)rank * 64 + (idx & 63);
        __half2 s2 = g_rs2[i2 * U + j];
        float2  c  = g_rc [i2 * U + j];
        __half2 an = g_ran[i2 * U + j];
        float4 p;
        p.x = __uint_as_float(*(const unsigned*)&s2);
        p.y = c.x; p.z = c.y;
        p.w = __uint_as_float(*(const unsigned*)&an);
        rec[idx] = p;
    }
    for (int idx = tid; idx < 32 * 64; idx += NTHR) {
        int i2 = idx >> 6;
        int j  = (int)rank * 64 + (idx & 63);
        __half2 s2 = g_ss2[i2 * U + j];
        float2  c  = g_sc [i2 * U + j];
        __half2 an = g_san[i2 * U + j];
        float4 p;
        p.x = __uint_as_float(*(const unsigned*)&s2);
        p.y = c.x; p.z = c.y;
        p.w = __uint_as_float(*(const unsigned*)&an);
        sen[idx] = p;
    }
    for (int idx = tid; idx < 2 * 8 * 256; idx += NTHR) vbuf[idx] = 0.f;
    __syncthreads();

    int bp = tid >> 6;            // batch-pair 0..3
    int jl = tid & 63;
    int jg = (int)rank * 64 + jl;
    int bg = blockIdx.x >> 2;     // cluster id
    float cmj  = cm[jg];
    float gl   = gleak[jg];
    float glvl = gl * vleak[jg];
    float CnR = g_CnR[jg], CdR = g_CdR[jg];
    float CnS = g_CnS[jg], CdS = g_CdS[jg];

    uint32_t vloc = smem_u32(vbuf);
    uint32_t vpeer[4];
    #pragma unroll
    for (int r = 0; r < 4; r++) vpeer[r] = mapa_rank(vloc, (uint32_t)r);

    float v0 = 0.f, v1 = 0.f;
    int p = 0;

    // cluster barrier: all CTAs' vbuf zero-init + params staged before first use
    asm volatile("barrier.cluster.arrive.aligned;" ::: "memory");
    asm volatile("barrier.cluster.wait.aligned;"   ::: "memory");

    for (int t = 0; t < TT; t++) {
        // stage this timestep's inputs (8 batches x 64 inputs) + timespans
        #pragma unroll
        for (int k = 0; k < 2; k++) {
            int idx = tid + k * NTHR;
            int bsx = idx >> 6, ii = idx & 63;
            xs[idx] = x[((size_t)(bg * 8 + bsx)) * TT * INP + t * INP + ii];
        }
        if (tid < 8) tss[tid] = ts[(size_t)(bg * 8 + tid) * TT + t];
        __syncthreads();

        float cmt0 = (6.0f * cmj) / tss[bp * 2];
        float cmt1 = (6.0f * cmj) / tss[bp * 2 + 1];

        // ---- sensory sums for both batches of this pair ----
        float sN0 = CnS, sD0 = CdS, sN1 = CnS, sD1 = CdS;
        const float* x0 = xs + (bp * 2) * 64;
        const float* x1 = x0 + 64;
        #pragma unroll 4
        for (int i2 = 0; i2 < 32; i2++) {
            float4 pp = sen[i2 * 64 + jl];
            unsigned s2u = __float_as_uint(pp.x), anu = __float_as_uint(pp.w);
            float2 s2 = __half22float2(*(const __half2*)&s2u);
            float2 an = __half22float2(*(const __half2*)&anu);
            float2 xa = *(const float2*)(x0 + 2 * i2);
            float2 xb = *(const float2*)(x1 + 2 * i2);
            float t00 = tanh_ap(fmaf(s2.x, xa.x, pp.y));
            float t01 = tanh_ap(fmaf(s2.y, xa.y, pp.z));
            float t10 = tanh_ap(fmaf(s2.x, xb.x, pp.y));
            float t11 = tanh_ap(fmaf(s2.y, xb.y, pp.z));
            float ax = fabsf(an.x), ay = fabsf(an.y);
            sN0 = fmaf(an.x, t00, sN0); sD0 = fmaf(ax, t00, sD0);
            sN0 = fmaf(an.y, t01, sN0); sD0 = fmaf(ay, t01, sD0);
            sN1 = fmaf(an.x, t10, sN1); sD1 = fmaf(ax, t10, sD1);
            sN1 = fmaf(an.y, t11, sN1); sD1 = fmaf(ay, t11, sD1);
        }
        float bN0 = glvl + CnR + sN0, bD0 = cmt0 + gl + CdR + sD0 + EPSV;
        float bN1 = glvl + CnR + sN1, bD1 = cmt1 + gl + CdR + sD1 + EPSV;

        // ---- 6 semi-implicit Euler unfolds ----
        for (int u = 0; u < UNFOLDS; u++) {
            float aN0 = 0.f, aD0 = 0.f, aN1 = 0.f, aD1 = 0.f;
            const float* vr0 = vbuf + (p * 8 + bp * 2) * 256;
            const float* vr1 = vr0 + 256;
            #pragma unroll 4
            for (int i2 = 0; i2 < 128; i2++) {
                float4 pp = rec[i2 * 64 + jl];
                unsigned s2u = __float_as_uint(pp.x), anu = __float_as_uint(pp.w);
                float2 s2 = __half22float2(*(const __half2*)&s2u);
                float2 an = __half22float2(*(const __half2*)&anu);
                float2 va = *(const float2*)(vr0 + 2 * i2);
                float2 vb = *(const float2*)(vr1 + 2 * i2);
                float t00 = tanh_ap(fmaf(s2.x, va.x, pp.y));
                float t01 = tanh_ap(fmaf(s2.y, va.y, pp.z));
                float t10 = tanh_ap(fmaf(s2.x, vb.x, pp.y));
                float t11 = tanh_ap(fmaf(s2.y, vb.y, pp.z));
                float ax = fabsf(an.x), ay = fabsf(an.y);
                aN0 = fmaf(an.x, t00, aN0); aD0 = fmaf(ax, t00, aD0);
                aN0 = fmaf(an.y, t01, aN0); aD0 = fmaf(ay, t01, aD0);
                aN1 = fmaf(an.x, t10, aN1); aD1 = fmaf(ax, t10, aD1);
                aN1 = fmaf(an.y, t11, aN1); aD1 = fmaf(ay, t11, aD1);
            }
            v0 = fmaf(cmt0, v0, bN0 + aN0) / (bD0 + aD0);
            v1 = fmaf(cmt1, v1, bN1 + aN1) / (bD1 + aD1);

            // publish new v to all 4 CTAs' copies (buffer p^1)
            uint32_t off = ((uint32_t)((p ^ 1) * 8 + bp * 2) * 256 + (uint32_t)jg) * 4;
            #pragma unroll
            for (int r = 0; r < 4; r++) {
                st_cluster_f32(vpeer[r] + off, v0);
                st_cluster_f32(vpeer[r] + off + 1024, v1);
            }
            asm volatile("barrier.cluster.arrive.aligned;" ::: "memory");
            asm volatile("barrier.cluster.wait.aligned;"   ::: "memory");
            p ^= 1;
        }
    }

    // ---- head: out[b] = sum_j (v*ow + ob)*hw + hb ----
    int r0 = bp * 2, r1 = r0 + 1;
    red[r0 * 64 + jl] = fmaf(v0, ow[jg], ob[jg]) * hw[jg];
    red[r1 * 64 + jl] = fmaf(v1, ow[jg], ob[jg]) * hw[jg];
    __syncthreads();
    #pragma unroll
    for (int s = 32; s > 0; s >>= 1) {
        if (jl < s) {
            red[r0 * 64 + jl] += red[r0 * 64 + jl + s];
            red[r1 * 64 + jl] += red[r1 * 64 + jl + s];
        }
        __syncthreads();
    }
    if (jl == 0) {
        uint32_t pa = mapa_rank(smem_u32(part), 0);
        st_cluster_f32(pa + (rank * 8 + (uint32_t)r0) * 4, red[r0 * 64]);
        st_cluster_f32(pa + (rank * 8 + (uint32_t)r1) * 4, red[r1 * 64]);
    }
    asm volatile("barrier.cluster.arrive.aligned;" ::: "memory");
    asm volatile("barrier.cluster.wait.aligned;"   ::: "memory");
    if (rank == 0 && tid < 8) {
        out[bg * 8 + tid] = part[tid] + part[8 + tid] + part[16 + tid] + part[24 + tid] + hb[0];
    }
}

// ---------------- launch ----------------
extern "C" void kernel_launch(void* const* d_in, const int* in_sizes, int n_in,
                              void* d_out, int out_size) {
    const float* x     = (const float*)d_in[0];
    const float* ts    = (const float*)d_in[1];
    const float* smu   = (const float*)d_in[2];
    const float* ssg   = (const float*)d_in[3];
    const float* sw    = (const float*)d_in[4];
    const float* ser   = (const float*)d_in[5];
    const float* mu    = (const float*)d_in[6];
    const float* sg    = (const float*)d_in[7];
    const float* w     = (const float*)d_in[8];
    const float* er    = (const float*)d_in[9];
    const float* gleak = (const float*)d_in[10];
    const float* vleak = (const float*)d_in[11];
    const float* cm    = (const float*)d_in[12];
    const float* iw    = (const float*)d_in[13];
    const float* ib    = (const float*)d_in[14];
    const float* ow    = (const float*)d_in[15];
    const float* ob    = (const float*)d_in[16];
    const float* hw    = (const float*)d_in[17];
    const float* hb    = (const float*)d_in[18];
    float* out = (float*)d_out;

    cudaFuncSetAttribute(ltc_main, cudaFuncAttributeMaxDynamicSharedMemorySize, SMEM_BYTES);

    prep_rec<<<(U * U + 255) / 256, 256>>>(mu, sg, w, er);
    prep_rec_cols<<<1, U>>>(w, er);
    prep_sens<<<(INP * U + 255) / 256, 256>>>(smu, ssg, sw, ser, iw, ib);
    prep_sens_cols<<<1, U>>>(sw, ser);
    // 256 batches / 8 per cluster = 32 clusters = 128 CTAs
    ltc_main<<<BB / 8 * 4, NTHR, SMEM_BYTES>>>(x, ts, gleak, vleak, cm, ow, ob, hw, hb, out);
}

// round 7
// speedup vs baseline: 2.5742x; 1.0195x over previous
#include <cuda_runtime.h>
#include <cuda_fp16.h>
#include <cstdint>
#include <cstddef>

#define U   256
#define INP 64
#define TT  128
#define BB  256
#define UNFOLDS 6
#define EPSV 1e-8f
#define NTHR 256          // 4 batch-pairs x 64 j-columns

// smem layout offsets (bytes)
#define OFF_RECA   0                       // float4[128*64]  = 131072 (s2e,s2o,ce,co)
#define OFF_RECAN  131072                  // half2 [128*64]  = 32768  (an e,o)
#define OFF_SENA   163840                  // float4[32*64]   = 32768
#define OFF_SENAN  196608                  // half2 [32*64]   = 8192
#define OFF_VBUF   204800                  // f32 [2][8][256] = 16384
#define OFF_XS     221184                  // f32 [8][64]     = 2048
#define OFF_TSS    223232                  // f32 [8]         = 32
#define OFF_RED    223264                  // f32 [8][64]     = 2048
#define OFF_PART   225312                  // f32 [4][8]      = 128
#define SMEM_BYTES 225440

// packed params in device globals (prep output)
__device__ float4  g_rpA[(U/2) * U];       // (s2 even, s2 odd, c even, c odd) fp32
__device__ __half2 g_rAn[(U/2) * U];       // (an even, an odd) half
__device__ float4  g_spA[(INP/2) * U];
__device__ __half2 g_sAn[(INP/2) * U];
__device__ float g_CnR[U], g_CdR[U], g_CnS[U], g_CdS[U];

__device__ __forceinline__ float tanh_ap(float x) {
    float r;
    asm("tanh.approx.f32 %0, %1;" : "=f"(r) : "f"(x));
    return r;
}
__device__ __forceinline__ uint32_t smem_u32(const void* p) {
    uint32_t a;
    asm("{ .reg .u64 t; cvta.to.shared.u64 t, %1; cvt.u32.u64 %0, t; }" : "=r"(a) : "l"(p));
    return a;
}
__device__ __forceinline__ uint32_t mapa_rank(uint32_t a, uint32_t r) {
    uint32_t o;
    asm("mapa.shared::cluster.u32 %0, %1, %2;" : "=r"(o) : "r"(a), "r"(r));
    return o;
}
__device__ __forceinline__ void st_cluster_f32(uint32_t a, float v) {
    asm volatile("st.shared::cluster.f32 [%0], %1;" :: "r"(a), "f"(v) : "memory");
}

// ---------------- fused prep kernel ----------------
// grid = 256 blocks (one per output column j), 256 threads (one per pre-neuron i).
__global__ void prep_all(const float* __restrict__ mu,  const float* __restrict__ sg,
                         const float* __restrict__ w,   const float* __restrict__ er,
                         const float* __restrict__ smu, const float* __restrict__ ssg,
                         const float* __restrict__ sw,  const float* __restrict__ ser,
                         const float* __restrict__ iw,  const float* __restrict__ ib) {
    int j = blockIdx.x;
    int i = threadIdx.x;
    __shared__ float rn[256], rd[256], sn[64], sd[64];

    // recurrent edge (i, j)
    {
        int idx = i * U + j;
        float s2 = 0.5f * sg[idx];
        float c  = -s2 * mu[idx];
        float a  = 0.5f * w[idx];
        float an = a * er[idx];
        int i2 = i >> 1, lo = i & 1;
        float* pa = (float*)&g_rpA[i2 * U + j];
        pa[lo]     = s2;
        pa[2 + lo] = c;
        ((__half*)&g_rAn[i2 * U + j])[lo] = __float2half_rn(an);
        rn[i] = an;
        rd[i] = a;
    }
    // sensory edge (i, j) for i < 64 (input_w/input_b folded in)
    if (i < INP) {
        int idx = i * U + j;
        float hs = 0.5f * ssg[idx];
        float s2 = hs * iw[i];
        float c  = hs * (ib[i] - smu[idx]);
        float a  = 0.5f * sw[idx];
        float an = a * ser[idx];
        int i2 = i >> 1, lo = i & 1;
        float* pa = (float*)&g_spA[i2 * U + j];
        pa[lo]     = s2;
        pa[2 + lo] = c;
        ((__half*)&g_sAn[i2 * U + j])[lo] = __float2half_rn(an);
        sn[i] = an;
        sd[i] = a;
    }
    __syncthreads();
    // reduce recurrent col sums (256) and sensory col sums (64)
    #pragma unroll
    for (int s = 128; s > 0; s >>= 1) {
        if (i < s) { rn[i] += rn[i + s]; rd[i] += rd[i + s]; }
        if (s <= 32 && i < s) { sn[i] += sn[i + s]; sd[i] += sd[i + s]; }
        __syncthreads();
    }
    if (i == 0) {
        g_CnR[j] = rn[0]; g_CdR[j] = rd[0];
        g_CnS[j] = sn[0]; g_CdS[j] = sd[0];
    }
}

// ---------------- main recurrence kernel ----------------
// 4-CTA cluster covers 8 batches; CTA rank r owns j in [r*64, r*64+64).
__global__ void __launch_bounds__(NTHR, 1) __cluster_dims__(4, 1, 1)
ltc_main(const float* __restrict__ x, const float* __restrict__ ts,
         const float* __restrict__ gleak, const float* __restrict__ vleak,
         const float* __restrict__ cm,
         const float* __restrict__ ow, const float* __restrict__ ob,
         const float* __restrict__ hw, const float* __restrict__ hb,
         float* __restrict__ out)
{
    extern __shared__ char dsm[];
    float4*  recA  = (float4*)(dsm + OFF_RECA);
    __half2* recAn = (__half2*)(dsm + OFF_RECAN);
    float4*  senA  = (float4*)(dsm + OFF_SENA);
    __half2* senAn = (__half2*)(dsm + OFF_SENAN);
    float*   vbuf  = (float*)(dsm + OFF_VBUF);
    float*   xs    = (float*)(dsm + OFF_XS);
    float*   tss   = (float*)(dsm + OFF_TSS);
    float*   red   = (float*)(dsm + OFF_RED);
    float*   part  = (float*)(dsm + OFF_PART);

    int tid = threadIdx.x;
    uint32_t rank;
    asm("mov.u32 %0, %%cluster_ctarank;" : "=r"(rank));

    // ---- stage parameters for this CTA's 64 columns ----
    for (int idx = tid; idx < 128 * 64; idx += NTHR) {
        int i2 = idx >> 6;
        int j  = (int)rank * 64 + (idx & 63);
        recA[idx]  = g_rpA[i2 * U + j];
        recAn[idx] = g_rAn[i2 * U + j];
    }
    for (int idx = tid; idx < 32 * 64; idx += NTHR) {
        int i2 = idx >> 6;
        int j  = (int)rank * 64 + (idx & 63);
        senA[idx]  = g_spA[i2 * U + j];
        senAn[idx] = g_sAn[i2 * U + j];
    }
    for (int idx = tid; idx < 2 * 8 * 256; idx += NTHR) vbuf[idx] = 0.f;
    __syncthreads();

    int bp = tid >> 6;            // batch-pair 0..3
    int jl = tid & 63;
    int jg = (int)rank * 64 + jl;
    int bg = blockIdx.x >> 2;     // cluster id
    float cmj  = cm[jg];
    float gl   = gleak[jg];
    float glvl = gl * vleak[jg];
    float CnR = g_CnR[jg], CdR = g_CdR[jg];
    float CnS = g_CnS[jg], CdS = g_CdS[jg];

    uint32_t vloc = smem_u32(vbuf);
    uint32_t vpeer[4];
    #pragma unroll
    for (int r = 0; r < 4; r++) vpeer[r] = mapa_rank(vloc, (uint32_t)r);

    float v0 = 0.f, v1 = 0.f;
    int p = 0;

    asm volatile("barrier.cluster.arrive.aligned;" ::: "memory");
    asm volatile("barrier.cluster.wait.aligned;"   ::: "memory");

    for (int t = 0; t < TT; t++) {
        // stage raw inputs + timespans
        #pragma unroll
        for (int k = 0; k < 2; k++) {
            int idx = tid + k * NTHR;
            int bsx = idx >> 6, ii = idx & 63;
            xs[idx] = x[((size_t)(bg * 8 + bsx)) * TT * INP + t * INP + ii];
        }
        if (tid < 8) tss[tid] = ts[(size_t)(bg * 8 + tid) * TT + t];
        __syncthreads();

        float cmt0 = __fdividef(6.0f * cmj, tss[bp * 2]);
        float cmt1 = __fdividef(6.0f * cmj, tss[bp * 2 + 1]);

        // ---- sensory sums (full fp32, 32 iters) ----
        float sN0 = CnS, sD0 = CdS, sN1 = CnS, sD1 = CdS;
        const float* x0 = xs + (bp * 2) * 64;
        const float* x1 = x0 + 64;
        #pragma unroll 8
        for (int i2 = 0; i2 < 32; i2++) {
            float4 pa = senA[i2 * 64 + jl];
            float2 an = __half22float2(senAn[i2 * 64 + jl]);
            float2 xa = *(const float2*)(x0 + 2 * i2);
            float2 xb = *(const float2*)(x1 + 2 * i2);
            float t00 = tanh_ap(fmaf(pa.x, xa.x, pa.z));
            float t01 = tanh_ap(fmaf(pa.y, xa.y, pa.w));
            float t10 = tanh_ap(fmaf(pa.x, xb.x, pa.z));
            float t11 = tanh_ap(fmaf(pa.y, xb.y, pa.w));
            sN0 = fmaf(an.x, t00, sN0); sD0 = fmaf(fabsf(an.x), t00, sD0);
            sN0 = fmaf(an.y, t01, sN0); sD0 = fmaf(fabsf(an.y), t01, sD0);
            sN1 = fmaf(an.x, t10, sN1); sD1 = fmaf(fabsf(an.x), t10, sD1);
            sN1 = fmaf(an.y, t11, sN1); sD1 = fmaf(fabsf(an.y), t11, sD1);
        }
        float bN0 = glvl + CnR + sN0, bD0 = cmt0 + gl + CdR + sD0 + EPSV;
        float bN1 = glvl + CnR + sN1, bD1 = cmt1 + gl + CdR + sD1 + EPSV;

        // ---- 6 semi-implicit Euler unfolds ----
        for (int u = 0; u < UNFOLDS; u++) {
            float aN0 = 0.f, aD0 = 0.f, aN1 = 0.f, aD1 = 0.f;
            const float* vr0 = vbuf + (p * 8 + bp * 2) * 256;
            const float* vr1 = vr0 + 256;
            #pragma unroll 8
            for (int i2 = 0; i2 < 128; i2++) {
                float4 pa = recA[i2 * 64 + jl];
                float2 an = __half22float2(recAn[i2 * 64 + jl]);
                float2 va = *(const float2*)(vr0 + 2 * i2);
                float2 vb = *(const float2*)(vr1 + 2 * i2);
                float t00 = tanh_ap(fmaf(pa.x, va.x, pa.z));
                float t01 = tanh_ap(fmaf(pa.y, va.y, pa.w));
                float t10 = tanh_ap(fmaf(pa.x, vb.x, pa.z));
                float t11 = tanh_ap(fmaf(pa.y, vb.y, pa.w));
                aN0 = fmaf(an.x, t00, aN0); aD0 = fmaf(fabsf(an.x), t00, aD0);
                aN0 = fmaf(an.y, t01, aN0); aD0 = fmaf(fabsf(an.y), t01, aD0);
                aN1 = fmaf(an.x, t10, aN1); aD1 = fmaf(fabsf(an.x), t10, aD1);
                aN1 = fmaf(an.y, t11, aN1); aD1 = fmaf(fabsf(an.y), t11, aD1);
            }
            v0 = __fdividef(fmaf(cmt0, v0, bN0 + aN0), bD0 + aD0);
            v1 = __fdividef(fmaf(cmt1, v1, bN1 + aN1), bD1 + aD1);

            // publish new fp32 v to all 4 CTAs (buffer p^1)
            uint32_t off = ((uint32_t)((p ^ 1) * 8 + bp * 2) * 256 + (uint32_t)jg) * 4;
            #pragma unroll
            for (int r = 0; r < 4; r++) {
                st_cluster_f32(vpeer[r] + off, v0);
                st_cluster_f32(vpeer[r] + off + 1024, v1);
            }
            asm volatile("barrier.cluster.arrive.aligned;" ::: "memory");
            asm volatile("barrier.cluster.wait.aligned;"   ::: "memory");
            p ^= 1;
        }
    }

    // ---- head: out[b] = sum_j (v*ow + ob)*hw + hb ----
    int r0 = bp * 2, r1 = r0 + 1;
    red[r0 * 64 + jl] = fmaf(v0, ow[jg], ob[jg]) * hw[jg];
    red[r1 * 64 + jl] = fmaf(v1, ow[jg], ob[jg]) * hw[jg];
    __syncthreads();
    #pragma unroll
    for (int s = 32; s > 0; s >>= 1) {
        if (jl < s) {
            red[r0 * 64 + jl] += red[r0 * 64 + jl + s];
            red[r1 * 64 + jl] += red[r1 * 64 + jl + s];
        }
        __syncthreads();
    }
    if (jl == 0) {
        uint32_t pa = mapa_rank(smem_u32(part), 0);
        st_cluster_f32(pa + (rank * 8 + (uint32_t)r0) * 4, red[r0 * 64]);
        st_cluster_f32(pa + (rank * 8 + (uint32_t)r1) * 4, red[r1 * 64]);
    }
    asm volatile("barrier.cluster.arrive.aligned;" ::: "memory");
    asm volatile("barrier.cluster.wait.aligned;"   ::: "memory");
    if (rank == 0 && tid < 8) {
        out[bg * 8 + tid] = part[tid] + part[8 + tid] + part[16 + tid] + part[24 + tid] + hb[0];
    }
}

// ---------------- launch ----------------
extern "C" void kernel_launch(void* const* d_in, const int* in_sizes, int n_in,
                              void* d_out, int out_size) {
    const float* x     = (const float*)d_in[0];
    const float* ts    = (const float*)d_in[1];
    const float* smu   = (const float*)d_in[2];
    const float* ssg   = (const float*)d_in[3];
    const float* sw    = (const float*)d_in[4];
    const float* ser   = (const float*)d_in[5];
    const float* mu    = (const float*)d_in[6];
    const float* sg    = (const float*)d_in[7];
    const float* w     = (const float*)d_in[8];
    const float* er    = (const float*)d_in[9];
    const float* gleak = (const float*)d_in[10];
    const float* vleak = (const float*)d_in[11];
    const float* cm    = (const float*)d_in[12];
    const float* iw    = (const float*)d_in[13];
    const float* ib    = (const float*)d_in[14];
    const float* ow    = (const float*)d_in[15];
    const float* ob    = (const float*)d_in[16];
    const float* hw    = (const float*)d_in[17];
    const float* hb    = (const float*)d_in[18];
    float* out = (float*)d_out;

    cudaFuncSetAttribute(ltc_main, cudaFuncAttributeMaxDynamicSharedMemorySize, SMEM_BYTES);

    prep_all<<<U, 256>>>(mu, sg, w, er, smu, ssg, sw, ser, iw, ib);
    ltc_main<<<BB / 8 * 4, NTHR, SMEM_BYTES>>>(x, ts, gleak, vleak, cm,
                                               ow, ob, hw, hb, out);
}